// round 16
// baseline (speedup 1.0000x reference)
#include <cuda_runtime.h>
#include <cuda_bf16.h>
#include <cstdint>

#define NB 32
#define L  2048
#define D  64
#define BM 64
#define BN 64
#define NT (L / BN)

// pre-split K/V scratch (bf16 hi/lo)
__device__ __align__(16) __nv_bfloat16 g_khi[NB * L * D];
__device__ __align__(16) __nv_bfloat16 g_klo[NB * L * D];
__device__ __align__(16) __nv_bfloat16 g_vhi[NB * L * D];
__device__ __align__(16) __nv_bfloat16 g_vlo[NB * L * D];
// packed masks: per (b,row,tile): x=maskbits[0:32) y=maskbits[32:64) z=diag0bits[0:32) w=diag0bits[32:64)
__device__ __align__(16) uint4 g_pk[NB * L * NT];
__device__ int g_mflag;   // 1 = mask is int32, 0 = uint8
// blocked raw-S scratch: per (block, tile, thread) 32 contiguous floats (8 x uint4)
__device__ __align__(16) float g_s[(size_t)NB * (L / BM) * NT * 128 * 32];

// dynamic smem: two 18 KB tile buffers (K in pass A, V in pass B)
#define SM_BUF_STRIDE 18432
#define SM_LO_OFF     9216
#define SMEM_BYTES    36864

__device__ __forceinline__ uint32_t pack2(__nv_bfloat16 a, __nv_bfloat16 b) {
    return (uint32_t)__bfloat16_as_ushort(a) | ((uint32_t)__bfloat16_as_ushort(b) << 16);
}

__device__ __forceinline__ void split2(float x, float y, uint32_t& hi, uint32_t& lo) {
    __nv_bfloat16 hx = __float2bfloat16(x);
    __nv_bfloat16 hy = __float2bfloat16(y);
    float rx = x - __bfloat162float(hx);
    float ry = y - __bfloat162float(hy);
    hi = pack2(hx, hy);
    lo = pack2(__float2bfloat16(rx), __float2bfloat16(ry));
}

__device__ __forceinline__ void cvt4(float4 f, uint2& hi, uint2& lo) {
    split2(f.x, f.y, hi.x, lo.x);
    split2(f.z, f.w, hi.y, lo.y);
}

__device__ __forceinline__ void mma_bf16(float c[4], const uint32_t a[4], uint32_t b0, uint32_t b1) {
    asm volatile(
        "mma.sync.aligned.m16n8k16.row.col.f32.bf16.bf16.f32 "
        "{%0,%1,%2,%3}, {%4,%5,%6,%7}, {%8,%9}, {%0,%1,%2,%3};\n"
        : "+f"(c[0]), "+f"(c[1]), "+f"(c[2]), "+f"(c[3])
        : "r"(a[0]), "r"(a[1]), "r"(a[2]), "r"(a[3]), "r"(b0), "r"(b1));
}

__device__ __forceinline__ void ldsm4(uint32_t& r0, uint32_t& r1, uint32_t& r2, uint32_t& r3,
                                      uint32_t addr) {
    asm volatile("ldmatrix.sync.aligned.m8n8.x4.shared.b16 {%0,%1,%2,%3}, [%4];\n"
                 : "=r"(r0), "=r"(r1), "=r"(r2), "=r"(r3) : "r"(addr));
}
__device__ __forceinline__ void ldsm4t(uint32_t& r0, uint32_t& r1, uint32_t& r2, uint32_t& r3,
                                       uint32_t addr) {
    asm volatile("ldmatrix.sync.aligned.m8n8.x4.trans.shared.b16 {%0,%1,%2,%3}, [%4];\n"
                 : "=r"(r0), "=r"(r1), "=r"(r2), "=r"(r3) : "r"(addr));
}

__device__ __forceinline__ void cpasync16(uint32_t dst, const void* src) {
    asm volatile("cp.async.cg.shared.global [%0], [%1], 16;\n" :: "r"(dst), "l"(src));
}
#define CP_COMMIT() asm volatile("cp.async.commit_group;\n" ::: "memory")
#define CP_WAIT(n)  asm volatile("cp.async.wait_group %0;\n" :: "n"(n) : "memory")

__global__ void probe_mask(const uint8_t* __restrict__ bm) {
    __shared__ int cnt;
    if (threadIdx.x == 0) cnt = 0;
    __syncthreads();
    int c = 0;
    for (int i = threadIdx.x; i < 4096; i += blockDim.x)
        if ((i & 3) != 0 && bm[i] != 0) c++;
    atomicAdd(&cnt, c);
    __syncthreads();
    if (threadIdx.x == 0) g_mflag = (cnt == 0) ? 1 : 0;
}

// fused: K/V fp32 -> split bf16 conversion  +  mask bit-packing (high-MLP version)
// grid MUST be <<<8192, 256>>>.
#define PK_NW (8192 * 256 / 32)   // 65536 warps; 2,097,152 row-tiles / 65536 = 32 iters
#define KV_F4 (NB * L * D / 4)    // 1,048,576 float4s in K (and in V)
__global__ void __launch_bounds__(256)
pack_and_split(const float* __restrict__ k, const float* __restrict__ v,
               const int* __restrict__ dmask, const uint8_t* __restrict__ bmask)
{
    const unsigned gid = blockIdx.x * 256u + threadIdx.x;

    // ---- presplit part: one float4 of K and V for the first KV_F4 threads ----
    if (gid < KV_F4) {
        unsigned i = gid;
        float4 k4 = __ldcs(reinterpret_cast<const float4*>(k) + i);
        float4 v4 = __ldcs(reinterpret_cast<const float4*>(v) + i);
        uint2 h, lo;
        cvt4(k4, h, lo);
        reinterpret_cast<uint2*>(g_khi)[i] = h;
        reinterpret_cast<uint2*>(g_klo)[i] = lo;
        cvt4(v4, h, lo);
        reinterpret_cast<uint2*>(g_vhi)[i] = h;
        reinterpret_cast<uint2*>(g_vlo)[i] = lo;
    }

    // ---- pack part: 32 row-tiles per warp, unrolled x4 with hoisted loads ----
    const bool mi32 = (g_mflag != 0);
    const int  lane = threadIdx.x & 31;
    const int  w0   = gid >> 5;
    const int* bi   = reinterpret_cast<const int*>(bmask);

    if (mi32) {
        #pragma unroll
        for (int it = 0; it < 32; it += 4) {
            int rt[4], da[4], db[4], ma[4], mb[4];
            #pragma unroll
            for (int u = 0; u < 4; u++) {
                rt[u] = w0 + (it + u) * PK_NW;
                size_t base = (size_t)(rt[u] >> 5) * L + (size_t)(rt[u] & 31) * 64;
                da[u] = __ldcs(dmask + base + lane);
                db[u] = __ldcs(dmask + base + 32 + lane);
                ma[u] = __ldcs(bi + base + lane);
                mb[u] = __ldcs(bi + base + 32 + lane);
            }
            #pragma unroll
            for (int u = 0; u < 4; u++) {
                uint32_t z0 = __ballot_sync(0xffffffffu, da[u] == 0);
                uint32_t z1 = __ballot_sync(0xffffffffu, db[u] == 0);
                uint32_t m0 = __ballot_sync(0xffffffffu, ma[u] != 0);
                uint32_t m1 = __ballot_sync(0xffffffffu, mb[u] != 0);
                if (lane == 0) g_pk[rt[u]] = make_uint4(m0, m1, z0, z1);
            }
        }
    } else {
        #pragma unroll
        for (int it = 0; it < 32; it += 4) {
            int rt[4];
            uint8_t da[4], db[4], ma[4], mb[4];
            #pragma unroll
            for (int u = 0; u < 4; u++) {
                rt[u] = w0 + (it + u) * PK_NW;
                size_t base = (size_t)(rt[u] >> 5) * L + (size_t)(rt[u] & 31) * 64;
                da[u] = (uint8_t)(__ldcs(dmask + base + lane) == 0 ? 1 : 0);
                db[u] = (uint8_t)(__ldcs(dmask + base + 32 + lane) == 0 ? 1 : 0);
                ma[u] = __ldcs(bmask + base + lane);
                mb[u] = __ldcs(bmask + base + 32 + lane);
            }
            #pragma unroll
            for (int u = 0; u < 4; u++) {
                uint32_t z0 = __ballot_sync(0xffffffffu, da[u] != 0);
                uint32_t z1 = __ballot_sync(0xffffffffu, db[u] != 0);
                uint32_t m0 = __ballot_sync(0xffffffffu, ma[u] != 0);
                uint32_t m1 = __ballot_sync(0xffffffffu, mb[u] != 0);
                if (lane == 0) g_pk[rt[u]] = make_uint4(m0, m1, z0, z1);
            }
        }
    }
}

// stage one 64x64 split-bf16 tile (hi+lo) into a smem buffer; one commit_group
__device__ __forceinline__ void stageT(uint32_t dstB, const __nv_bfloat16* sh,
                                       const __nv_bfloat16* sl, int s_r, int s_c) {
    #pragma unroll
    for (int i = 0; i < 4; i++) {
        int rr = s_r + i * 16;
        cpasync16(dstB + rr * 144 + s_c * 2,             sh + rr * 64 + s_c);
        cpasync16(dstB + SM_LO_OFF + rr * 144 + s_c * 2, sl + rr * 64 + s_c);
    }
    CP_COMMIT();
}

// QK^T split-bf16 tile (hi*hi + hi*lo + lo*hi)
#define QK_TILE(kHiB, kLoB, sAcc)                                              \
    _Pragma("unroll")                                                          \
    for (int nt = 0; nt < 8; nt++)                                             \
        sAcc[nt][0] = sAcc[nt][1] = sAcc[nt][2] = sAcc[nt][3] = 0.f;           \
    _Pragma("unroll")                                                          \
    for (int nt = 0; nt < 8; nt++) {                                           \
        uint32_t rowOff = (uint32_t)(nt * 8 + tl) * 144u;                      \
        _Pragma("unroll")                                                      \
        for (int p = 0; p < 2; p++) {                                          \
            uint32_t off = rowOff + (uint32_t)(p * 32 + tq * 8) * 2u;          \
            uint32_t bh0, bh1, bh2, bh3, bl0, bl1, bl2, bl3;                   \
            ldsm4(bh0, bh1, bh2, bh3, (kHiB) + off);                           \
            ldsm4(bl0, bl1, bl2, bl3, (kLoB) + off);                           \
            mma_bf16(sAcc[nt], &aQh[(2*p  )*4], bh0, bh1);                     \
            mma_bf16(sAcc[nt], &aQh[(2*p  )*4], bl0, bl1);                     \
            mma_bf16(sAcc[nt], &aQl[(2*p  )*4], bh0, bh1);                     \
            mma_bf16(sAcc[nt], &aQh[(2*p+1)*4], bh2, bh3);                     \
            mma_bf16(sAcc[nt], &aQh[(2*p+1)*4], bl2, bl3);                     \
            mma_bf16(sAcc[nt], &aQl[(2*p+1)*4], bh2, bh3);                     \
        }                                                                      \
    }

#define APPLY_MASKS(sAcc, pk0, pk1)                                            \
    _Pragma("unroll")                                                          \
    for (int nt = 0; nt < 8; nt++) {                                           \
        uint32_t mw0 = (nt < 4) ? pk0.x : pk0.y;                               \
        uint32_t zw0 = (nt < 4) ? pk0.z : pk0.w;                               \
        uint32_t mw1 = (nt < 4) ? pk1.x : pk1.y;                               \
        uint32_t zw1 = (nt < 4) ? pk1.z : pk1.w;                               \
        int sh = (nt & 3) * 8 + quad * 2;                                      \
        if ((mw0 >> sh) & 1)       sAcc[nt][0] = -INFINITY;                    \
        if ((zw0 >> sh) & 1)       sAcc[nt][0] = -1e32f;                       \
        if ((mw0 >> (sh + 1)) & 1) sAcc[nt][1] = -INFINITY;                    \
        if ((zw0 >> (sh + 1)) & 1) sAcc[nt][1] = -1e32f;                       \
        if ((mw1 >> sh) & 1)       sAcc[nt][2] = -INFINITY;                    \
        if ((zw1 >> sh) & 1)       sAcc[nt][2] = -1e32f;                       \
        if ((mw1 >> (sh + 1)) & 1) sAcc[nt][3] = -INFINITY;                    \
        if ((zw1 >> (sh + 1)) & 1) sAcc[nt][3] = -1e32f;                       \
    }

__global__ void __launch_bounds__(128, 3)
attn_fused(const float* __restrict__ q,
           float* __restrict__ out, float* __restrict__ attn)
{
    extern __shared__ char smem_raw[];
    const uint32_t smB = (uint32_t)__cvta_generic_to_shared(smem_raw);

    const int b    = blockIdx.y;
    const int q0   = blockIdx.x * BM;
    const int tid  = threadIdx.x;
    const int warp = tid >> 5;
    const int lane = tid & 31;
    const int g    = lane >> 2;
    const int quad = lane & 3;
    const int tq   = lane >> 3;
    const int tl   = lane & 7;
    const int rl0  = warp * 16 + g;
    const int row0 = q0 + rl0;
    const int row1 = row0 + 8;

    const int s_r  = tid >> 3;
    const int s_c  = (tid & 7) << 3;

    const size_t kvBase = ((size_t)b * L) * D;
    float*       attnb  = attn + (size_t)b * L * L;
    const uint4* pkr0   = g_pk + ((size_t)b * L + row0) * NT;
    const uint4* pkr1   = g_pk + ((size_t)b * L + row1) * NT;
    // blocked S scratch for this block: [NT][128][32] floats
    float*       sBlk   = g_s + ((size_t)(b * (L / BM) + blockIdx.x) * NT) * 128 * 32;

    // ---- stage K0 (pass A prologue) ----
    stageT(smB, g_khi + kvBase, g_klo + kvBase, s_r, s_c);

    // ---- Q A-fragments (hi/lo split), temperature folded in (x2^-3 exact) ----
    uint32_t aQh[16], aQl[16];
    {
        const float* qb = q + kvBase;
        #pragma unroll
        for (int ks = 0; ks < 4; ks++) {
            int c0 = ks * 16 + quad * 2;
            float2 x0 = *reinterpret_cast<const float2*>(qb + (size_t)row0 * D + c0);
            float2 x1 = *reinterpret_cast<const float2*>(qb + (size_t)row1 * D + c0);
            float2 x2 = *reinterpret_cast<const float2*>(qb + (size_t)row0 * D + c0 + 8);
            float2 x3 = *reinterpret_cast<const float2*>(qb + (size_t)row1 * D + c0 + 8);
            split2(x0.x * 0.125f, x0.y * 0.125f, aQh[ks*4+0], aQl[ks*4+0]);
            split2(x1.x * 0.125f, x1.y * 0.125f, aQh[ks*4+1], aQl[ks*4+1]);
            split2(x2.x * 0.125f, x2.y * 0.125f, aQh[ks*4+2], aQl[ks*4+2]);
            split2(x3.x * 0.125f, x3.y * 0.125f, aQh[ks*4+3], aQl[ks*4+3]);
        }
    }

    float mrun0 = -INFINITY, mrun1 = -INFINITY;
    float lrun0 = 0.f, lrun1 = 0.f;

    // ========== PASS A: QK^T + masks + stats; store masked raw S (blocked, streaming) ==========
    for (int j = 0; j < NT; j++) {
        const uint32_t kHiB = smB + (j & 1) * SM_BUF_STRIDE;
        const uint32_t kLoB = kHiB + SM_LO_OFF;

        CP_WAIT(0);
        __syncthreads();
        if (j + 1 < NT)
            stageT(smB + ((j + 1) & 1) * SM_BUF_STRIDE,
                   g_khi + kvBase + (size_t)(j + 1) * BN * D,
                   g_klo + kvBase + (size_t)(j + 1) * BN * D, s_r, s_c);

        // prefetch mask bits before the MMA block (latency cover; stream-once)
        uint4 pk0 = __ldcs(pkr0 + j);
        uint4 pk1 = __ldcs(pkr1 + j);

        float sAcc[8][4];
        QK_TILE(kHiB, kLoB, sAcc)

        APPLY_MASKS(sAcc, pk0, pk1)

        // store masked raw S: 8 contiguous 16B streaming stores per thread
        {
            float4* sdst = reinterpret_cast<float4*>(sBlk + (size_t)j * 128 * 32 + tid * 32);
            #pragma unroll
            for (int nt = 0; nt < 8; nt++)
                __stcs(sdst + nt, make_float4(sAcc[nt][0], sAcc[nt][1], sAcc[nt][2], sAcc[nt][3]));
        }

        float tmax0 = -INFINITY, tmax1 = -INFINITY;
        #pragma unroll
        for (int nt = 0; nt < 8; nt++) {
            tmax0 = fmaxf(tmax0, fmaxf(sAcc[nt][0], sAcc[nt][1]));
            tmax1 = fmaxf(tmax1, fmaxf(sAcc[nt][2], sAcc[nt][3]));
        }
        tmax0 = fmaxf(tmax0, __shfl_xor_sync(0xffffffffu, tmax0, 1));
        tmax0 = fmaxf(tmax0, __shfl_xor_sync(0xffffffffu, tmax0, 2));
        tmax1 = fmaxf(tmax1, __shfl_xor_sync(0xffffffffu, tmax1, 1));
        tmax1 = fmaxf(tmax1, __shfl_xor_sync(0xffffffffu, tmax1, 2));

        float mnew0 = fmaxf(mrun0, tmax0);
        float mnew1 = fmaxf(mrun1, tmax1);
        float alpha0 = (mnew0 == -INFINITY) ? 1.0f : __expf(mrun0 - mnew0);
        float alpha1 = (mnew1 == -INFINITY) ? 1.0f : __expf(mrun1 - mnew1);
        mrun0 = mnew0; mrun1 = mnew1;

        float rs0 = 0.f, rs1 = 0.f;
        #pragma unroll
        for (int nt = 0; nt < 8; nt++) {
            rs0 += __expf(sAcc[nt][0] - mnew0) + __expf(sAcc[nt][1] - mnew0);
            rs1 += __expf(sAcc[nt][2] - mnew1) + __expf(sAcc[nt][3] - mnew1);
        }
        rs0 += __shfl_xor_sync(0xffffffffu, rs0, 1);
        rs0 += __shfl_xor_sync(0xffffffffu, rs0, 2);
        rs1 += __shfl_xor_sync(0xffffffffu, rs1, 1);
        rs1 += __shfl_xor_sync(0xffffffffu, rs1, 2);
        lrun0 = lrun0 * alpha0 + rs0;
        lrun1 = lrun1 * alpha1 + rs1;
    }

    const float mfin0 = mrun0, mfin1 = mrun1;
    const float invl0 = 1.0f / lrun0;
    const float invl1 = 1.0f / lrun1;

    // ========== PASS B: read S back (coalesced), finalize p, PV ==========
    __syncthreads();   // all warps done with pass A buffers before restaging as V
    stageT(smB,                 g_vhi + kvBase, g_vlo + kvBase, s_r, s_c);
    stageT(smB + SM_BUF_STRIDE, g_vhi + kvBase + BN * D, g_vlo + kvBase + BN * D, s_r, s_c);

    float oAcc[8][4];
    #pragma unroll
    for (int i = 0; i < 8; i++)
        oAcc[i][0] = oAcc[i][1] = oAcc[i][2] = oAcc[i][3] = 0.f;

    for (int j = 0; j < NT; j++) {
        const uint32_t vHiB = smB + (j & 1) * SM_BUF_STRIDE;
        const uint32_t vLoB = vHiB + SM_LO_OFF;

        // issue S reads first (coalesced 16B streaming loads; covered by V wait + sync)
        float sAcc[8][4];
        {
            const float4* ssrc = reinterpret_cast<const float4*>(sBlk + (size_t)j * 128 * 32 + tid * 32);
            #pragma unroll
            for (int nt = 0; nt < 8; nt++) {
                float4 sv = __ldcs(ssrc + nt);
                sAcc[nt][0] = sv.x; sAcc[nt][1] = sv.y;
                sAcc[nt][2] = sv.z; sAcc[nt][3] = sv.w;
            }
        }

        if (j < NT - 1) { CP_WAIT(1); } else { CP_WAIT(0); }
        __syncthreads();

        // final normalized p, written once (streaming; never re-read)
        #pragma unroll
        for (int nt = 0; nt < 8; nt++) {
            float p0 = __expf(sAcc[nt][0] - mfin0) * invl0;
            float p1 = __expf(sAcc[nt][1] - mfin0) * invl0;
            float p2 = __expf(sAcc[nt][2] - mfin1) * invl1;
            float p3 = __expf(sAcc[nt][3] - mfin1) * invl1;
            int col = j * BN + nt * 8 + quad * 2;
            __stcs(reinterpret_cast<float2*>(attnb + (size_t)row0 * L + col), make_float2(p0, p1));
            __stcs(reinterpret_cast<float2*>(attnb + (size_t)row1 * L + col), make_float2(p2, p3));
            sAcc[nt][0] = p0; sAcc[nt][1] = p1; sAcc[nt][2] = p2; sAcc[nt][3] = p3;
        }

        // PV (V[j] resident)
        #pragma unroll
        for (int kn = 0; kn < 4; kn++) {
            uint32_t pah[4], pal[4];
            split2(sAcc[2*kn  ][0], sAcc[2*kn  ][1], pah[0], pal[0]);
            split2(sAcc[2*kn  ][2], sAcc[2*kn  ][3], pah[1], pal[1]);
            split2(sAcc[2*kn+1][0], sAcc[2*kn+1][1], pah[2], pal[2]);
            split2(sAcc[2*kn+1][2], sAcc[2*kn+1][3], pah[3], pal[3]);
            uint32_t rowOff = (uint32_t)(kn * 16 + (tq & 1) * 8 + tl) * 144u;
            #pragma unroll
            for (int dtp = 0; dtp < 4; dtp++) {
                uint32_t off = rowOff + (uint32_t)(dtp * 16 + (tq >> 1) * 8) * 2u;
                uint32_t bh0, bh1, bh2, bh3, bl0, bl1, bl2, bl3;
                ldsm4t(bh0, bh1, bh2, bh3, vHiB + off);
                ldsm4t(bl0, bl1, bl2, bl3, vLoB + off);
                mma_bf16(oAcc[2*dtp  ], pah, bh0, bh1);
                mma_bf16(oAcc[2*dtp  ], pah, bl0, bl1);
                mma_bf16(oAcc[2*dtp  ], pal, bh0, bh1);
                mma_bf16(oAcc[2*dtp+1], pah, bh2, bh3);
                mma_bf16(oAcc[2*dtp+1], pah, bl2, bl3);
                mma_bf16(oAcc[2*dtp+1], pal, bh2, bh3);
            }
        }

        // re-stage V[j+2] into this buffer (holds V[j], consumed above)
        if (j + 2 < NT) {
            __syncthreads();
            const size_t tb = kvBase + (size_t)(j + 2) * BN * D;
            stageT(vHiB, g_vhi + tb, g_vlo + tb, s_r, s_c);
        }
    }

    // ---- O epilogue (p already carried 1/l) ----
    float* ob = out + ((size_t)b * L) * D;
    #pragma unroll
    for (int dt = 0; dt < 8; dt++) {
        int dc = dt * 8 + quad * 2;
        *reinterpret_cast<float2*>(ob + (size_t)row0 * D + dc) =
            make_float2(oAcc[dt][0], oAcc[dt][1]);
        *reinterpret_cast<float2*>(ob + (size_t)row1 * D + dc) =
            make_float2(oAcc[dt][2], oAcc[dt][3]);
    }
}

extern "C" void kernel_launch(void* const* d_in, const int* in_sizes, int n_in,
                              void* d_out, int out_size)
{
    // Robust binding by element count: q,k,v = NB*L*D; diag_mask, mask = NB*L*L.
    const int SMALL = NB * L * D;
    const void* small_p[3] = {nullptr, nullptr, nullptr};
    const void* big_p[2]   = {nullptr, nullptr};
    int ns = 0, nb = 0;
    for (int i = 0; i < n_in; i++) {
        if (in_sizes[i] == SMALL) { if (ns < 3) small_p[ns++] = d_in[i]; }
        else                      { if (nb < 2) big_p[nb++]   = d_in[i]; }
    }
    const float*   q, *k, *v;
    const int*     dm;
    const uint8_t* bm;
    if (ns == 3 && nb == 2) {
        q  = (const float*)small_p[0];
        k  = (const float*)small_p[1];
        v  = (const float*)small_p[2];
        dm = (const int*)big_p[0];
        bm = (const uint8_t*)big_p[1];
    } else {
        q  = (const float*)d_in[0];
        k  = (const float*)d_in[1];
        v  = (const float*)d_in[2];
        dm = (const int*)d_in[3];
        bm = (const uint8_t*)d_in[4];
    }

    float* out  = (float*)d_out;                      // [B, L, D] first
    float* attn = out + (size_t)NB * L * D;           // then [B, L, L]

    cudaFuncSetAttribute(attn_fused, cudaFuncAttributeMaxDynamicSharedMemorySize, SMEM_BYTES);

    probe_mask<<<1, 256>>>(bm);
    pack_and_split<<<8192, 256>>>(k, v, dm, bm);
    dim3 grid(L / BM, NB);
    attn_fused<<<grid, 128, SMEM_BYTES>>>(q, out, attn);
}

// round 17
// speedup vs baseline: 1.1876x; 1.1876x over previous
#include <cuda_runtime.h>
#include <cuda_bf16.h>
#include <cstdint>

#define NB 32
#define L  2048
#define D  64
#define BM 64
#define BN 64
#define NT (L / BN)

// pre-split K/V scratch (bf16 hi/lo)
__device__ __align__(16) __nv_bfloat16 g_khi[NB * L * D];
__device__ __align__(16) __nv_bfloat16 g_klo[NB * L * D];
__device__ __align__(16) __nv_bfloat16 g_vhi[NB * L * D];
__device__ __align__(16) __nv_bfloat16 g_vlo[NB * L * D];
// packed masks: per (b,row,tile): x=maskbits[0:32) y=maskbits[32:64) z=diag0bits[0:32) w=diag0bits[32:64)
__device__ __align__(16) uint4 g_pk[NB * L * NT];
__device__ int g_mflag;   // 1 = mask is int32, 0 = uint8

// dynamic smem: three 18 KB tile buffers (K double-buf in pass A, V triple-buf in pass B)
#define SM_BUF_STRIDE 18432
#define SM_LO_OFF     9216
#define SMEM_BYTES    55296

__device__ __forceinline__ uint32_t pack2(__nv_bfloat16 a, __nv_bfloat16 b) {
    return (uint32_t)__bfloat16_as_ushort(a) | ((uint32_t)__bfloat16_as_ushort(b) << 16);
}

__device__ __forceinline__ void split2(float x, float y, uint32_t& hi, uint32_t& lo) {
    __nv_bfloat16 hx = __float2bfloat16(x);
    __nv_bfloat16 hy = __float2bfloat16(y);
    float rx = x - __bfloat162float(hx);
    float ry = y - __bfloat162float(hy);
    hi = pack2(hx, hy);
    lo = pack2(__float2bfloat16(rx), __float2bfloat16(ry));
}

__device__ __forceinline__ void cvt4(float4 f, uint2& hi, uint2& lo) {
    split2(f.x, f.y, hi.x, lo.x);
    split2(f.z, f.w, hi.y, lo.y);
}

__device__ __forceinline__ void mma_bf16(float c[4], const uint32_t a[4], uint32_t b0, uint32_t b1) {
    asm volatile(
        "mma.sync.aligned.m16n8k16.row.col.f32.bf16.bf16.f32 "
        "{%0,%1,%2,%3}, {%4,%5,%6,%7}, {%8,%9}, {%0,%1,%2,%3};\n"
        : "+f"(c[0]), "+f"(c[1]), "+f"(c[2]), "+f"(c[3])
        : "r"(a[0]), "r"(a[1]), "r"(a[2]), "r"(a[3]), "r"(b0), "r"(b1));
}

__device__ __forceinline__ void ldsm4(uint32_t& r0, uint32_t& r1, uint32_t& r2, uint32_t& r3,
                                      uint32_t addr) {
    asm volatile("ldmatrix.sync.aligned.m8n8.x4.shared.b16 {%0,%1,%2,%3}, [%4];\n"
                 : "=r"(r0), "=r"(r1), "=r"(r2), "=r"(r3) : "r"(addr));
}
__device__ __forceinline__ void ldsm4t(uint32_t& r0, uint32_t& r1, uint32_t& r2, uint32_t& r3,
                                       uint32_t addr) {
    asm volatile("ldmatrix.sync.aligned.m8n8.x4.trans.shared.b16 {%0,%1,%2,%3}, [%4];\n"
                 : "=r"(r0), "=r"(r1), "=r"(r2), "=r"(r3) : "r"(addr));
}

__device__ __forceinline__ void cpasync16(uint32_t dst, const void* src) {
    asm volatile("cp.async.cg.shared.global [%0], [%1], 16;\n" :: "r"(dst), "l"(src));
}
#define CP_COMMIT() asm volatile("cp.async.commit_group;\n" ::: "memory")
#define CP_WAIT(n)  asm volatile("cp.async.wait_group %0;\n" :: "n"(n) : "memory")

__global__ void probe_mask(const uint8_t* __restrict__ bm) {
    __shared__ int cnt;
    if (threadIdx.x == 0) cnt = 0;
    __syncthreads();
    int c = 0;
    for (int i = threadIdx.x; i < 4096; i += blockDim.x)
        if ((i & 3) != 0 && bm[i] != 0) c++;
    atomicAdd(&cnt, c);
    __syncthreads();
    if (threadIdx.x == 0) g_mflag = (cnt == 0) ? 1 : 0;
}

// fused: K/V fp32 -> split bf16 conversion  +  mask bit-packing (high-MLP version)
// grid MUST be <<<8192, 256>>>.
#define PK_NW (8192 * 256 / 32)   // 65536 warps; 2,097,152 row-tiles / 65536 = 32 iters
#define KV_F4 (NB * L * D / 4)    // 1,048,576 float4s in K (and in V)
__global__ void __launch_bounds__(256)
pack_and_split(const float* __restrict__ k, const float* __restrict__ v,
               const int* __restrict__ dmask, const uint8_t* __restrict__ bmask)
{
    const unsigned gid = blockIdx.x * 256u + threadIdx.x;

    // ---- presplit part: one float4 of K and V for the first KV_F4 threads ----
    if (gid < KV_F4) {
        unsigned i = gid;
        float4 k4 = __ldcs(reinterpret_cast<const float4*>(k) + i);
        float4 v4 = __ldcs(reinterpret_cast<const float4*>(v) + i);
        uint2 h, lo;
        cvt4(k4, h, lo);
        reinterpret_cast<uint2*>(g_khi)[i] = h;
        reinterpret_cast<uint2*>(g_klo)[i] = lo;
        cvt4(v4, h, lo);
        reinterpret_cast<uint2*>(g_vhi)[i] = h;
        reinterpret_cast<uint2*>(g_vlo)[i] = lo;
    }

    // ---- pack part: 32 row-tiles per warp, unrolled x4 with hoisted loads ----
    const bool mi32 = (g_mflag != 0);
    const int  lane = threadIdx.x & 31;
    const int  w0   = gid >> 5;
    const int* bi   = reinterpret_cast<const int*>(bmask);

    if (mi32) {
        #pragma unroll
        for (int it = 0; it < 32; it += 4) {
            int rt[4], da[4], db[4], ma[4], mb[4];
            #pragma unroll
            for (int u = 0; u < 4; u++) {
                rt[u] = w0 + (it + u) * PK_NW;
                size_t base = (size_t)(rt[u] >> 5) * L + (size_t)(rt[u] & 31) * 64;
                da[u] = __ldcs(dmask + base + lane);
                db[u] = __ldcs(dmask + base + 32 + lane);
                ma[u] = __ldcs(bi + base + lane);
                mb[u] = __ldcs(bi + base + 32 + lane);
            }
            #pragma unroll
            for (int u = 0; u < 4; u++) {
                uint32_t z0 = __ballot_sync(0xffffffffu, da[u] == 0);
                uint32_t z1 = __ballot_sync(0xffffffffu, db[u] == 0);
                uint32_t m0 = __ballot_sync(0xffffffffu, ma[u] != 0);
                uint32_t m1 = __ballot_sync(0xffffffffu, mb[u] != 0);
                if (lane == 0) g_pk[rt[u]] = make_uint4(m0, m1, z0, z1);
            }
        }
    } else {
        #pragma unroll
        for (int it = 0; it < 32; it += 4) {
            int rt[4];
            uint8_t da[4], db[4], ma[4], mb[4];
            #pragma unroll
            for (int u = 0; u < 4; u++) {
                rt[u] = w0 + (it + u) * PK_NW;
                size_t base = (size_t)(rt[u] >> 5) * L + (size_t)(rt[u] & 31) * 64;
                da[u] = (uint8_t)(__ldcs(dmask + base + lane) == 0 ? 1 : 0);
                db[u] = (uint8_t)(__ldcs(dmask + base + 32 + lane) == 0 ? 1 : 0);
                ma[u] = __ldcs(bmask + base + lane);
                mb[u] = __ldcs(bmask + base + 32 + lane);
            }
            #pragma unroll
            for (int u = 0; u < 4; u++) {
                uint32_t z0 = __ballot_sync(0xffffffffu, da[u] != 0);
                uint32_t z1 = __ballot_sync(0xffffffffu, db[u] != 0);
                uint32_t m0 = __ballot_sync(0xffffffffu, ma[u] != 0);
                uint32_t m1 = __ballot_sync(0xffffffffu, mb[u] != 0);
                if (lane == 0) g_pk[rt[u]] = make_uint4(m0, m1, z0, z1);
            }
        }
    }
}

// stage one 64x64 split-bf16 tile (hi+lo) into a smem buffer; one commit_group
__device__ __forceinline__ void stageT(uint32_t dstB, const __nv_bfloat16* sh,
                                       const __nv_bfloat16* sl, int s_r, int s_c) {
    #pragma unroll
    for (int i = 0; i < 4; i++) {
        int rr = s_r + i * 16;
        cpasync16(dstB + rr * 144 + s_c * 2,             sh + rr * 64 + s_c);
        cpasync16(dstB + SM_LO_OFF + rr * 144 + s_c * 2, sl + rr * 64 + s_c);
    }
    CP_COMMIT();
}

// QK^T split-bf16 tile (hi*hi + hi*lo + lo*hi)
#define QK_TILE(kHiB, kLoB, sAcc)                                              \
    _Pragma("unroll")                                                          \
    for (int nt = 0; nt < 8; nt++)                                             \
        sAcc[nt][0] = sAcc[nt][1] = sAcc[nt][2] = sAcc[nt][3] = 0.f;           \
    _Pragma("unroll")                                                          \
    for (int nt = 0; nt < 8; nt++) {                                           \
        uint32_t rowOff = (uint32_t)(nt * 8 + tl) * 144u;                      \
        _Pragma("unroll")                                                      \
        for (int p = 0; p < 2; p++) {                                          \
            uint32_t off = rowOff + (uint32_t)(p * 32 + tq * 8) * 2u;          \
            uint32_t bh0, bh1, bh2, bh3, bl0, bl1, bl2, bl3;                   \
            ldsm4(bh0, bh1, bh2, bh3, (kHiB) + off);                           \
            ldsm4(bl0, bl1, bl2, bl3, (kLoB) + off);                           \
            mma_bf16(sAcc[nt], &aQh[(2*p  )*4], bh0, bh1);                     \
            mma_bf16(sAcc[nt], &aQh[(2*p  )*4], bl0, bl1);                     \
            mma_bf16(sAcc[nt], &aQl[(2*p  )*4], bh0, bh1);                     \
            mma_bf16(sAcc[nt], &aQh[(2*p+1)*4], bh2, bh3);                     \
            mma_bf16(sAcc[nt], &aQh[(2*p+1)*4], bl2, bl3);                     \
            mma_bf16(sAcc[nt], &aQl[(2*p+1)*4], bh2, bh3);                     \
        }                                                                      \
    }

#define APPLY_MASKS(sAcc, pk0, pk1)                                            \
    _Pragma("unroll")                                                          \
    for (int nt = 0; nt < 8; nt++) {                                           \
        uint32_t mw0 = (nt < 4) ? pk0.x : pk0.y;                               \
        uint32_t zw0 = (nt < 4) ? pk0.z : pk0.w;                               \
        uint32_t mw1 = (nt < 4) ? pk1.x : pk1.y;                               \
        uint32_t zw1 = (nt < 4) ? pk1.z : pk1.w;                               \
        int sh = (nt & 3) * 8 + quad * 2;                                      \
        if ((mw0 >> sh) & 1)       sAcc[nt][0] = -INFINITY;                    \
        if ((zw0 >> sh) & 1)       sAcc[nt][0] = -1e32f;                       \
        if ((mw0 >> (sh + 1)) & 1) sAcc[nt][1] = -INFINITY;                    \
        if ((zw0 >> (sh + 1)) & 1) sAcc[nt][1] = -1e32f;                       \
        if ((mw1 >> sh) & 1)       sAcc[nt][2] = -INFINITY;                    \
        if ((zw1 >> sh) & 1)       sAcc[nt][2] = -1e32f;                       \
        if ((mw1 >> (sh + 1)) & 1) sAcc[nt][3] = -INFINITY;                    \
        if ((zw1 >> (sh + 1)) & 1) sAcc[nt][3] = -1e32f;                       \
    }

__global__ void __launch_bounds__(128, 3)
attn_fused(const float* __restrict__ q,
           float* __restrict__ out, float* __restrict__ attn)
{
    extern __shared__ char smem_raw[];
    const uint32_t smB = (uint32_t)__cvta_generic_to_shared(smem_raw);

    const int b    = blockIdx.y;
    const int q0   = blockIdx.x * BM;
    const int tid  = threadIdx.x;
    const int warp = tid >> 5;
    const int lane = tid & 31;
    const int g    = lane >> 2;
    const int quad = lane & 3;
    const int tq   = lane >> 3;
    const int tl   = lane & 7;
    const int rl0  = warp * 16 + g;
    const int row0 = q0 + rl0;
    const int row1 = row0 + 8;

    const int s_r  = tid >> 3;
    const int s_c  = (tid & 7) << 3;

    const size_t kvBase = ((size_t)b * L) * D;
    float*       attnb  = attn + (size_t)b * L * L;
    const uint4* pkr0   = g_pk + ((size_t)b * L + row0) * NT;
    const uint4* pkr1   = g_pk + ((size_t)b * L + row1) * NT;

    // ---- stage K0 (pass A prologue) ----
    stageT(smB, g_khi + kvBase, g_klo + kvBase, s_r, s_c);

    // ---- Q A-fragments (hi/lo split), temperature folded in (x2^-3 exact) ----
    uint32_t aQh[16], aQl[16];
    {
        const float* qb = q + kvBase;
        #pragma unroll
        for (int ks = 0; ks < 4; ks++) {
            int c0 = ks * 16 + quad * 2;
            float2 x0 = *reinterpret_cast<const float2*>(qb + (size_t)row0 * D + c0);
            float2 x1 = *reinterpret_cast<const float2*>(qb + (size_t)row1 * D + c0);
            float2 x2 = *reinterpret_cast<const float2*>(qb + (size_t)row0 * D + c0 + 8);
            float2 x3 = *reinterpret_cast<const float2*>(qb + (size_t)row1 * D + c0 + 8);
            split2(x0.x * 0.125f, x0.y * 0.125f, aQh[ks*4+0], aQl[ks*4+0]);
            split2(x1.x * 0.125f, x1.y * 0.125f, aQh[ks*4+1], aQl[ks*4+1]);
            split2(x2.x * 0.125f, x2.y * 0.125f, aQh[ks*4+2], aQl[ks*4+2]);
            split2(x3.x * 0.125f, x3.y * 0.125f, aQh[ks*4+3], aQl[ks*4+3]);
        }
    }

    float mrun0 = -INFINITY, mrun1 = -INFINITY;
    float lrun0 = 0.f, lrun1 = 0.f;

    // ========== PASS A: QK^T + masks + stats; store masked raw S to attn ==========
    for (int j = 0; j < NT; j++) {
        const uint32_t kHiB = smB + (j & 1) * SM_BUF_STRIDE;
        const uint32_t kLoB = kHiB + SM_LO_OFF;

        CP_WAIT(0);
        __syncthreads();
        if (j + 1 < NT)
            stageT(smB + ((j + 1) & 1) * SM_BUF_STRIDE,
                   g_khi + kvBase + (size_t)(j + 1) * BN * D,
                   g_klo + kvBase + (size_t)(j + 1) * BN * D, s_r, s_c);

        // prefetch mask bits before the MMA block (latency cover)
        uint4 pk0 = pkr0[j];
        uint4 pk1 = pkr1[j];

        float sAcc[8][4];
        QK_TILE(kHiB, kLoB, sAcc)

        APPLY_MASKS(sAcc, pk0, pk1)

        // store masked raw S (read back in pass B by the same thread; overwritten by p)
        #pragma unroll
        for (int nt = 0; nt < 8; nt++) {
            int col = j * BN + nt * 8 + quad * 2;
            *reinterpret_cast<float2*>(attnb + (size_t)row0 * L + col) =
                make_float2(sAcc[nt][0], sAcc[nt][1]);
            *reinterpret_cast<float2*>(attnb + (size_t)row1 * L + col) =
                make_float2(sAcc[nt][2], sAcc[nt][3]);
        }

        float tmax0 = -INFINITY, tmax1 = -INFINITY;
        #pragma unroll
        for (int nt = 0; nt < 8; nt++) {
            tmax0 = fmaxf(tmax0, fmaxf(sAcc[nt][0], sAcc[nt][1]));
            tmax1 = fmaxf(tmax1, fmaxf(sAcc[nt][2], sAcc[nt][3]));
        }
        tmax0 = fmaxf(tmax0, __shfl_xor_sync(0xffffffffu, tmax0, 1));
        tmax0 = fmaxf(tmax0, __shfl_xor_sync(0xffffffffu, tmax0, 2));
        tmax1 = fmaxf(tmax1, __shfl_xor_sync(0xffffffffu, tmax1, 1));
        tmax1 = fmaxf(tmax1, __shfl_xor_sync(0xffffffffu, tmax1, 2));

        float mnew0 = fmaxf(mrun0, tmax0);
        float mnew1 = fmaxf(mrun1, tmax1);
        float alpha0 = (mnew0 == -INFINITY) ? 1.0f : __expf(mrun0 - mnew0);
        float alpha1 = (mnew1 == -INFINITY) ? 1.0f : __expf(mrun1 - mnew1);
        mrun0 = mnew0; mrun1 = mnew1;

        float rs0 = 0.f, rs1 = 0.f;
        #pragma unroll
        for (int nt = 0; nt < 8; nt++) {
            rs0 += __expf(sAcc[nt][0] - mnew0) + __expf(sAcc[nt][1] - mnew0);
            rs1 += __expf(sAcc[nt][2] - mnew1) + __expf(sAcc[nt][3] - mnew1);
        }
        rs0 += __shfl_xor_sync(0xffffffffu, rs0, 1);
        rs0 += __shfl_xor_sync(0xffffffffu, rs0, 2);
        rs1 += __shfl_xor_sync(0xffffffffu, rs1, 1);
        rs1 += __shfl_xor_sync(0xffffffffu, rs1, 2);
        lrun0 = lrun0 * alpha0 + rs0;
        lrun1 = lrun1 * alpha1 + rs1;
    }

    const float mfin0 = mrun0, mfin1 = mrun1;
    const float invl0 = 1.0f / lrun0;
    const float invl1 = 1.0f / lrun1;

    // ========== PASS B: read S back, finalize p, PV (V triple-buffered, 1 sync/tile) ==========
    __syncthreads();   // all warps done with pass A buffers before restaging as V
    stageT(smB,                 g_vhi + kvBase, g_vlo + kvBase, s_r, s_c);
    stageT(smB + SM_BUF_STRIDE, g_vhi + kvBase + BN * D, g_vlo + kvBase + BN * D, s_r, s_c);

    float oAcc[8][4];
    #pragma unroll
    for (int i = 0; i < 8; i++)
        oAcc[i][0] = oAcc[i][1] = oAcc[i][2] = oAcc[i][3] = 0.f;

    for (int j = 0; j < NT; j++) {
        const uint32_t vHiB = smB + (uint32_t)(j % 3) * SM_BUF_STRIDE;
        const uint32_t vLoB = vHiB + SM_LO_OFF;

        // issue S reads first (own addresses; latency covered by V wait + sync)
        float sAcc[8][4];
        #pragma unroll
        for (int nt = 0; nt < 8; nt++) {
            int col = j * BN + nt * 8 + quad * 2;
            float2 a = *reinterpret_cast<const float2*>(attnb + (size_t)row0 * L + col);
            float2 c = *reinterpret_cast<const float2*>(attnb + (size_t)row1 * L + col);
            sAcc[nt][0] = a.x; sAcc[nt][1] = a.y;
            sAcc[nt][2] = c.x; sAcc[nt][3] = c.y;
        }

        if (j < NT - 1) { CP_WAIT(1); } else { CP_WAIT(0); }
        __syncthreads();

        // stage V[j+2] into buffer (j+2)%3 — holds V[j-1], consumed by all warps
        // (this sync is after every warp's iter j-1 PV), so overwrite is safe.
        if (j + 2 < NT) {
            const size_t tb = kvBase + (size_t)(j + 2) * BN * D;
            stageT(smB + (uint32_t)((j + 2) % 3) * SM_BUF_STRIDE,
                   g_vhi + tb, g_vlo + tb, s_r, s_c);
        }

        // final normalized p, written once (overwrites raw S in-place: L2-hot)
        #pragma unroll
        for (int nt = 0; nt < 8; nt++) {
            float p0 = __expf(sAcc[nt][0] - mfin0) * invl0;
            float p1 = __expf(sAcc[nt][1] - mfin0) * invl0;
            float p2 = __expf(sAcc[nt][2] - mfin1) * invl1;
            float p3 = __expf(sAcc[nt][3] - mfin1) * invl1;
            int col = j * BN + nt * 8 + quad * 2;
            *reinterpret_cast<float2*>(attnb + (size_t)row0 * L + col) = make_float2(p0, p1);
            *reinterpret_cast<float2*>(attnb + (size_t)row1 * L + col) = make_float2(p2, p3);
            sAcc[nt][0] = p0; sAcc[nt][1] = p1; sAcc[nt][2] = p2; sAcc[nt][3] = p3;
        }

        // PV (V[j] resident)
        #pragma unroll
        for (int kn = 0; kn < 4; kn++) {
            uint32_t pah[4], pal[4];
            split2(sAcc[2*kn  ][0], sAcc[2*kn  ][1], pah[0], pal[0]);
            split2(sAcc[2*kn  ][2], sAcc[2*kn  ][3], pah[1], pal[1]);
            split2(sAcc[2*kn+1][0], sAcc[2*kn+1][1], pah[2], pal[2]);
            split2(sAcc[2*kn+1][2], sAcc[2*kn+1][3], pah[3], pal[3]);
            uint32_t rowOff = (uint32_t)(kn * 16 + (tq & 1) * 8 + tl) * 144u;
            #pragma unroll
            for (int dtp = 0; dtp < 4; dtp++) {
                uint32_t off = rowOff + (uint32_t)(dtp * 16 + (tq >> 1) * 8) * 2u;
                uint32_t bh0, bh1, bh2, bh3, bl0, bl1, bl2, bl3;
                ldsm4t(bh0, bh1, bh2, bh3, vHiB + off);
                ldsm4t(bl0, bl1, bl2, bl3, vLoB + off);
                mma_bf16(oAcc[2*dtp  ], pah, bh0, bh1);
                mma_bf16(oAcc[2*dtp  ], pah, bl0, bl1);
                mma_bf16(oAcc[2*dtp  ], pal, bh0, bh1);
                mma_bf16(oAcc[2*dtp+1], pah, bh2, bh3);
                mma_bf16(oAcc[2*dtp+1], pah, bl2, bl3);
                mma_bf16(oAcc[2*dtp+1], pal, bh2, bh3);
            }
        }
    }

    // ---- O epilogue (p already carried 1/l) ----
    float* ob = out + ((size_t)b * L) * D;
    #pragma unroll
    for (int dt = 0; dt < 8; dt++) {
        int dc = dt * 8 + quad * 2;
        *reinterpret_cast<float2*>(ob + (size_t)row0 * D + dc) =
            make_float2(oAcc[dt][0], oAcc[dt][1]);
        *reinterpret_cast<float2*>(ob + (size_t)row1 * D + dc) =
            make_float2(oAcc[dt][2], oAcc[dt][3]);
    }
}

extern "C" void kernel_launch(void* const* d_in, const int* in_sizes, int n_in,
                              void* d_out, int out_size)
{
    // Robust binding by element count: q,k,v = NB*L*D; diag_mask, mask = NB*L*L.
    const int SMALL = NB * L * D;
    const void* small_p[3] = {nullptr, nullptr, nullptr};
    const void* big_p[2]   = {nullptr, nullptr};
    int ns = 0, nb = 0;
    for (int i = 0; i < n_in; i++) {
        if (in_sizes[i] == SMALL) { if (ns < 3) small_p[ns++] = d_in[i]; }
        else                      { if (nb < 2) big_p[nb++]   = d_in[i]; }
    }
    const float*   q, *k, *v;
    const int*     dm;
    const uint8_t* bm;
    if (ns == 3 && nb == 2) {
        q  = (const float*)small_p[0];
        k  = (const float*)small_p[1];
        v  = (const float*)small_p[2];
        dm = (const int*)big_p[0];
        bm = (const uint8_t*)big_p[1];
    } else {
        q  = (const float*)d_in[0];
        k  = (const float*)d_in[1];
        v  = (const float*)d_in[2];
        dm = (const int*)d_in[3];
        bm = (const uint8_t*)d_in[4];
    }

    float* out  = (float*)d_out;                      // [B, L, D] first
    float* attn = out + (size_t)NB * L * D;           // then [B, L, L]

    cudaFuncSetAttribute(attn_fused, cudaFuncAttributeMaxDynamicSharedMemorySize, SMEM_BYTES);

    probe_mask<<<1, 256>>>(bm);
    pack_and_split<<<8192, 256>>>(k, v, dm, bm);
    dim3 grid(L / BM, NB);
    attn_fused<<<grid, 128, SMEM_BYTES>>>(q, out, attn);
}